// round 5
// baseline (speedup 1.0000x reference)
#include <cuda_runtime.h>
#include <cstdint>

// Problem constants
#define NTOK 8192        // B*S
#define DDIM 1024
#define NEXP 8
#define EPSV 1e-4f
#define WTHR 0.1f

// Scratch (device globals)
__device__ int   g_cnt[NEXP];
__device__ int   g_tok[NEXP][NTOK];
__device__ float g_wt [NEXP][NTOK];

// ---------------------------------------------------------------------------
__global__ void zero_counts_kernel() {
    if (threadIdx.x < NEXP) g_cnt[threadIdx.x] = 0;
}

// ---------------------------------------------------------------------------
// Gating + bias epilogue, fused. One warp per token. gate_W cached in smem.
// ---------------------------------------------------------------------------
__global__ __launch_bounds__(256)
void gating_kernel(const float* __restrict__ x,
                   const float* __restrict__ gW,
                   const float* __restrict__ gb,
                   const float* __restrict__ eb,
                   float* __restrict__ out)
{
    __shared__ float4 sgw[DDIM * 2];              // [D][E] as 2 float4/row, 32KB
    const int tid  = threadIdx.x;
    const int lane = tid & 31;

    const float4* gW4 = reinterpret_cast<const float4*>(gW);
    for (int i = tid; i < DDIM * 2; i += 256) sgw[i] = gW4[i];
    __syncthreads();

    const int warp = blockIdx.x * 8 + (tid >> 5);
    const float* xr = x + (size_t)warp * DDIM;

    float acc[NEXP];
#pragma unroll
    for (int e = 0; e < NEXP; e++) acc[e] = 0.0f;

#pragma unroll 4
    for (int d = lane; d < DDIM; d += 32) {
        const float xv = __ldg(xr + d);
        const float4 ga = sgw[d * 2 + 0];
        const float4 gc = sgw[d * 2 + 1];
        acc[0] = fmaf(xv, ga.x, acc[0]);
        acc[1] = fmaf(xv, ga.y, acc[1]);
        acc[2] = fmaf(xv, ga.z, acc[2]);
        acc[3] = fmaf(xv, ga.w, acc[3]);
        acc[4] = fmaf(xv, gc.x, acc[4]);
        acc[5] = fmaf(xv, gc.y, acc[5]);
        acc[6] = fmaf(xv, gc.z, acc[6]);
        acc[7] = fmaf(xv, gc.w, acc[7]);
    }
#pragma unroll
    for (int e = 0; e < NEXP; e++) {
#pragma unroll
        for (int off = 16; off > 0; off >>= 1)
            acc[e] += __shfl_xor_sync(0xffffffffu, acc[e], off);
    }

    int   i0 = 0, i1 = 0;
    float w0 = 0.f, w1 = 0.f;
    if (lane == 0) {
        float s[NEXP], p[NEXP];
        float mx = -1e30f;
#pragma unroll
        for (int e = 0; e < NEXP; e++) {
            s[e] = fmaxf(acc[e] + gb[e], EPSV);   // TEMP = 1.0
            mx = fmaxf(mx, s[e]);
        }
        float Z = 0.0f;
#pragma unroll
        for (int e = 0; e < NEXP; e++) { p[e] = expf(s[e] - mx); Z += p[e]; }
        const float invZ = 1.0f / Z;
#pragma unroll
        for (int e = 0; e < NEXP; e++) p[e] *= invZ;

        // top-2, strict '>' => lowest index wins ties (JAX semantics)
#pragma unroll
        for (int e = 1; e < NEXP; e++) if (p[e] > p[i0]) i0 = e;
        float best = -1e30f;
#pragma unroll
        for (int e = 0; e < NEXP; e++)
            if (e != i0 && p[e] > best) { best = p[e]; i1 = e; }

        w0 = fmaxf(p[i0], WTHR);
        w1 = fmaxf(p[i1], WTHR);
        const float sc = 0.5f / (w0 + w1);        // includes /K
        w0 *= sc; w1 *= sc;

        int s0 = atomicAdd(&g_cnt[i0], 1);
        g_tok[i0][s0] = warp;  g_wt[i0][s0] = w0;
        int s1 = atomicAdd(&g_cnt[i1], 1);
        g_tok[i1][s1] = warp;  g_wt[i1][s1] = w1;
    }
    // broadcast routing to the warp, write bias row (initializes all of out)
    i0 = __shfl_sync(0xffffffffu, i0, 0);
    i1 = __shfl_sync(0xffffffffu, i1, 0);
    w0 = __shfl_sync(0xffffffffu, w0, 0);
    w1 = __shfl_sync(0xffffffffu, w1, 0);

    const float4* b0 = reinterpret_cast<const float4*>(eb + i0 * DDIM);
    const float4* b1 = reinterpret_cast<const float4*>(eb + i1 * DDIM);
    float4* o4 = reinterpret_cast<float4*>(out + (size_t)warp * DDIM);
#pragma unroll
    for (int j = lane; j < DDIM / 4; j += 32) {
        const float4 u = __ldg(b0 + j);
        const float4 v = __ldg(b1 + j);
        float4 r;
        r.x = w0 * u.x + w1 * v.x;
        r.y = w0 * u.y + w1 * v.y;
        r.z = w0 * u.z + w1 * v.z;
        r.w = w0 * u.w + w1 * v.w;
        o4[j] = r;
    }
}

// ---------------------------------------------------------------------------
// tf32 grouped GEMM: CTA 128x128x32, 4 warps (2x2), warp tile 64x64,
// cp.async 2-stage pipeline, swizzled A smem, fragment-path cvt to tf32.
// ---------------------------------------------------------------------------
#define BM 128
#define BN 128
#define BK 32
#define AW (BM * 32)          // A stage words (swizzled, stride 32)
#define BSTRIDE 136
#define BW (BK * BSTRIDE)     // B stage words
#define STAGE (AW + BW)       // 8448 words per stage
#define GEMM_SMEM (2 * STAGE * 4)

extern __shared__ float smx[];

__device__ __forceinline__ uint32_t f2tf32(float f) {
    uint32_t r;
    asm("cvt.rna.tf32.f32 %0, %1;" : "=r"(r) : "f"(f));
    return r;
}

__device__ __forceinline__ void mma_tf32(float& d0, float& d1, float& d2, float& d3,
                                         uint32_t a0, uint32_t a1, uint32_t a2, uint32_t a3,
                                         uint32_t b0, uint32_t b1)
{
    asm volatile(
        "mma.sync.aligned.m16n8k8.row.col.f32.tf32.tf32.f32 "
        "{%0,%1,%2,%3}, {%4,%5,%6,%7}, {%8,%9}, {%0,%1,%2,%3};"
        : "+f"(d0), "+f"(d1), "+f"(d2), "+f"(d3)
        : "r"(a0), "r"(a1), "r"(a2), "r"(a3), "r"(b0), "r"(b1));
}

__global__ __launch_bounds__(128, 2)
void expert_gemm_kernel(const float* __restrict__ x,
                        const float* __restrict__ eW,
                        float* __restrict__ out)
{
    const int e    = blockIdx.z;
    const int n    = g_cnt[e];
    const int row0 = blockIdx.y * BM;
    if (row0 >= n) return;
    const int col0 = blockIdx.x * BN;

    __shared__ int   stok[BM];
    __shared__ float swt[BM];

    const int tid  = threadIdx.x;
    const int lane = tid & 31;
    const int wid  = tid >> 5;
    const int wm   = wid & 1;        // 0..1 : 64-row group
    const int wn   = wid >> 1;       // 0..1 : 64-col group
    const int g    = lane >> 2;      // 0..7
    const int cq   = lane & 3;       // 0..3

    {
        const int r = row0 + tid;
        if (r < n) { stok[tid] = g_tok[e][r]; swt[tid] = g_wt[e][r]; }
        else       { stok[tid] = -1;          swt[tid] = 0.0f; }
    }
    __syncthreads();

    // per-thread cp.async sources/destinations
    const int mytok = stok[tid];
    const float* asrc = x + (size_t)(mytok < 0 ? 0 : mytok) * DDIM;
    const int sA = (tid ^ (tid >> 3)) & 7;                 // A store swizzle
    const float* We   = eW + (size_t)e * DDIM * DDIM;
    const int bk = tid >> 2, bc = tid & 3;
    const float* bsrc = We + (size_t)bk * DDIM + col0 + bc * 4;

    const uint32_t abase = (uint32_t)__cvta_generic_to_shared(smx) + tid * 128;
    const uint32_t bbase = (uint32_t)__cvta_generic_to_shared(smx + AW)
                         + (bk * BSTRIDE + bc * 4) * 4;

    float c[4][8][4];
#pragma unroll
    for (int mt = 0; mt < 4; mt++)
#pragma unroll
        for (int nt = 0; nt < 8; nt++)
#pragma unroll
            for (int i = 0; i < 4; i++) c[mt][nt][i] = 0.0f;

    auto load_tile = [&](int t) {
        const uint32_t off = (uint32_t)(t & 1) * (STAGE * 4);
        const float* as = asrc + t * BK;
#pragma unroll
        for (int j = 0; j < 8; j++)
            asm volatile("cp.async.cg.shared.global [%0], [%1], 16;"
                         :: "r"(abase + off + (uint32_t)((j ^ sA) << 4)), "l"(as + j * 4));
        const float* bs = bsrc + (size_t)t * BK * DDIM;
#pragma unroll
        for (int j = 0; j < 8; j++)
            asm volatile("cp.async.cg.shared.global [%0], [%1], 16;"
                         :: "r"(bbase + off + (uint32_t)(j * 64)), "l"(bs + j * 16));
    };

    load_tile(0);
    asm volatile("cp.async.commit_group;");

    const int NT = DDIM / BK;   // 32
    for (int i = 0; i < NT; i++) {
        if (i + 1 < NT) load_tile(i + 1);
        asm volatile("cp.async.commit_group;");
        asm volatile("cp.async.wait_group 1;");
        __syncthreads();

        const float* As = smx + (i & 1) * STAGE;
        const float* Bs = As + AW;

#pragma unroll
        for (int kb = 0; kb < 4; kb++) {
            const int kk  = kb * 8;
            const int k4a = kb * 2;             // (kk+cq)>>2, cq<4

            uint32_t af[4][4];
#pragma unroll
            for (int mt = 0; mt < 4; mt++) {
                const int m0 = wm * 64 + mt * 16 + g;
                const int m1 = m0 + 8;
                const int s0 = (m0 ^ (m0 >> 3)) & 7;
                const int s1 = (m1 ^ (m1 >> 3)) & 7;
                af[mt][0] = f2tf32(As[m0 * 32 + ((k4a       ^ s0) << 2) + cq]);
                af[mt][1] = f2tf32(As[m1 * 32 + ((k4a       ^ s1) << 2) + cq]);
                af[mt][2] = f2tf32(As[m0 * 32 + (((k4a + 1) ^ s0) << 2) + cq]);
                af[mt][3] = f2tf32(As[m1 * 32 + (((k4a + 1) ^ s1) << 2) + cq]);
            }
            uint32_t bf[8][2];
#pragma unroll
            for (int nt = 0; nt < 8; nt++) {
                const int nn = wn * 64 + nt * 8 + g;
                bf[nt][0] = f2tf32(Bs[(kk + cq)     * BSTRIDE + nn]);
                bf[nt][1] = f2tf32(Bs[(kk + cq + 4) * BSTRIDE + nn]);
            }
#pragma unroll
            for (int mt = 0; mt < 4; mt++)
#pragma unroll
                for (int nt = 0; nt < 8; nt++)
                    mma_tf32(c[mt][nt][0], c[mt][nt][1], c[mt][nt][2], c[mt][nt][3],
                             af[mt][0], af[mt][1], af[mt][2], af[mt][3],
                             bf[nt][0], bf[nt][1]);
        }
        __syncthreads();
    }

    // epilogue: scale by routing weight, atomic-accumulate into out
#pragma unroll
    for (int mt = 0; mt < 4; mt++) {
#pragma unroll
        for (int half = 0; half < 2; half++) {
            const int lr  = wm * 64 + mt * 16 + g + half * 8;
            const int tok = stok[lr];
            if (tok < 0) continue;
            const float w = swt[lr];
            float* ob = out + (size_t)tok * DDIM + col0 + wn * 64 + cq * 2;
#pragma unroll
            for (int nt = 0; nt < 8; nt++) {
                atomicAdd(ob + nt * 8 + 0, w * c[mt][nt][half * 2 + 0]);
                atomicAdd(ob + nt * 8 + 1, w * c[mt][nt][half * 2 + 1]);
            }
        }
    }
}

// ---------------------------------------------------------------------------
extern "C" void kernel_launch(void* const* d_in, const int* in_sizes, int n_in,
                              void* d_out, int out_size)
{
    const float* x  = (const float*)d_in[0];   // [4,2048,1024]
    const float* gW = (const float*)d_in[1];   // [1024,8]
    const float* gb = (const float*)d_in[2];   // [8]
    const float* eW = (const float*)d_in[3];   // [8,1024,1024]
    const float* eb = (const float*)d_in[4];   // [8,1024]
    float* out = (float*)d_out;                // [4,2048,1024]

    cudaFuncSetAttribute(expert_gemm_kernel,
                         cudaFuncAttributeMaxDynamicSharedMemorySize, GEMM_SMEM);

    zero_counts_kernel<<<1, 32>>>();
    gating_kernel<<<NTOK / 8, 256>>>(x, gW, gb, eb, out);
    dim3 grid(DDIM / BN, NTOK / BM, NEXP);     // (8, 64, 8); y-tiles beyond n exit
    expert_gemm_kernel<<<grid, 128, GEMM_SMEM>>>(x, eW, out);
}

// round 7
// speedup vs baseline: 1.7398x; 1.7398x over previous
#include <cuda_runtime.h>
#include <cstdint>

// Problem constants
#define NTOK 8192        // B*S
#define DDIM 1024
#define NEXP 8
#define EPSV 1e-4f
#define WTHR 0.1f

// Scratch (device globals)
__device__ int   g_cnt[NEXP];
__device__ int   g_tok[NEXP][NTOK];
__device__ float g_wt [NEXP][NTOK];

// ---------------------------------------------------------------------------
__global__ void zero_counts_kernel() {
    if (threadIdx.x < NEXP) g_cnt[threadIdx.x] = 0;
}

// ---------------------------------------------------------------------------
// Gating + bias epilogue, fused. One warp per token. gate_W cached in smem.
// (Identical routing math to the 330us-passing version.)
// ---------------------------------------------------------------------------
__global__ __launch_bounds__(256)
void gating_kernel(const float* __restrict__ x,
                   const float* __restrict__ gW,
                   const float* __restrict__ gb,
                   const float* __restrict__ eb,
                   float* __restrict__ out)
{
    __shared__ float4 sgw[DDIM * 2];              // [D][E] as 2 float4/row, 32KB
    const int tid  = threadIdx.x;
    const int lane = tid & 31;

    const float4* gW4 = reinterpret_cast<const float4*>(gW);
    for (int i = tid; i < DDIM * 2; i += 256) sgw[i] = gW4[i];
    __syncthreads();

    const int warp = blockIdx.x * 8 + (tid >> 5);
    const float* xr = x + (size_t)warp * DDIM;

    float acc[NEXP];
#pragma unroll
    for (int e = 0; e < NEXP; e++) acc[e] = 0.0f;

#pragma unroll 4
    for (int d = lane; d < DDIM; d += 32) {
        const float xv = __ldg(xr + d);
        const float4 ga = sgw[d * 2 + 0];
        const float4 gc = sgw[d * 2 + 1];
        acc[0] = fmaf(xv, ga.x, acc[0]);
        acc[1] = fmaf(xv, ga.y, acc[1]);
        acc[2] = fmaf(xv, ga.z, acc[2]);
        acc[3] = fmaf(xv, ga.w, acc[3]);
        acc[4] = fmaf(xv, gc.x, acc[4]);
        acc[5] = fmaf(xv, gc.y, acc[5]);
        acc[6] = fmaf(xv, gc.z, acc[6]);
        acc[7] = fmaf(xv, gc.w, acc[7]);
    }
#pragma unroll
    for (int e = 0; e < NEXP; e++) {
#pragma unroll
        for (int off = 16; off > 0; off >>= 1)
            acc[e] += __shfl_xor_sync(0xffffffffu, acc[e], off);
    }

    int   i0 = 0, i1 = 0;
    float w0 = 0.f, w1 = 0.f;
    if (lane == 0) {
        float s[NEXP], p[NEXP];
        float mx = -1e30f;
#pragma unroll
        for (int e = 0; e < NEXP; e++) {
            s[e] = fmaxf(acc[e] + gb[e], EPSV);   // TEMP = 1.0
            mx = fmaxf(mx, s[e]);
        }
        float Z = 0.0f;
#pragma unroll
        for (int e = 0; e < NEXP; e++) { p[e] = expf(s[e] - mx); Z += p[e]; }
        const float invZ = 1.0f / Z;
#pragma unroll
        for (int e = 0; e < NEXP; e++) p[e] *= invZ;

        // top-2, strict '>' => lowest index wins ties (JAX semantics)
#pragma unroll
        for (int e = 1; e < NEXP; e++) if (p[e] > p[i0]) i0 = e;
        float best = -1e30f;
#pragma unroll
        for (int e = 0; e < NEXP; e++)
            if (e != i0 && p[e] > best) { best = p[e]; i1 = e; }

        w0 = fmaxf(p[i0], WTHR);
        w1 = fmaxf(p[i1], WTHR);
        const float sc = 0.5f / (w0 + w1);        // includes /K
        w0 *= sc; w1 *= sc;

        int s0 = atomicAdd(&g_cnt[i0], 1);
        g_tok[i0][s0] = warp;  g_wt[i0][s0] = w0;
        int s1 = atomicAdd(&g_cnt[i1], 1);
        g_tok[i1][s1] = warp;  g_wt[i1][s1] = w1;
    }
    // broadcast routing, write bias row (initializes every out element)
    i0 = __shfl_sync(0xffffffffu, i0, 0);
    i1 = __shfl_sync(0xffffffffu, i1, 0);
    w0 = __shfl_sync(0xffffffffu, w0, 0);
    w1 = __shfl_sync(0xffffffffu, w1, 0);

    const float4* b0 = reinterpret_cast<const float4*>(eb + i0 * DDIM);
    const float4* b1 = reinterpret_cast<const float4*>(eb + i1 * DDIM);
    float4* o4 = reinterpret_cast<float4*>(out + (size_t)warp * DDIM);
#pragma unroll
    for (int j = lane; j < DDIM / 4; j += 32) {
        const float4 u = __ldg(b0 + j);
        const float4 v = __ldg(b1 + j);
        float4 r;
        r.x = w0 * u.x + w1 * v.x;
        r.y = w0 * u.y + w1 * v.y;
        r.z = w0 * u.z + w1 * v.z;
        r.w = w0 * u.w + w1 * v.w;
        o4[j] = r;
    }
}

// ---------------------------------------------------------------------------
// tf32 tensor-core grouped GEMM (round-2 structure + smem double buffer,
// ONE __syncthreads per K-tile).
// CTA 128x128x32, 8 warps (2 M x 4 N), warp tile 64x32 via m16n8k8.
// cvt to tf32 once on the reg->smem store path.
// ---------------------------------------------------------------------------
#define BM 128
#define BN 128
#define BK 32
#define ASTRIDE 36                 // bank = 4m + k : conflict-free frag loads
#define BSTRIDE 136                // bank = 8k + n : conflict-free frag loads
#define AWORDS (BM * ASTRIDE)      // 4608
#define BWORDS (BK * BSTRIDE)      // 4352
#define STAGEW (AWORDS + BWORDS)   // 8960 words/stage
#define GEMM_SMEM (2 * STAGEW * 4) // 71680 B

extern __shared__ uint32_t smu[];

__device__ __forceinline__ uint32_t f2tf32(float f) {
    uint32_t r;
    asm("cvt.rna.tf32.f32 %0, %1;" : "=r"(r) : "f"(f));
    return r;
}

__device__ __forceinline__ void mma_tf32(float& d0, float& d1, float& d2, float& d3,
                                         uint32_t a0, uint32_t a1, uint32_t a2, uint32_t a3,
                                         uint32_t b0, uint32_t b1)
{
    asm volatile(
        "mma.sync.aligned.m16n8k8.row.col.f32.tf32.tf32.f32 "
        "{%0,%1,%2,%3}, {%4,%5,%6,%7}, {%8,%9}, {%0,%1,%2,%3};"
        : "+f"(d0), "+f"(d1), "+f"(d2), "+f"(d3)
        : "r"(a0), "r"(a1), "r"(a2), "r"(a3), "r"(b0), "r"(b1));
}

__global__ __launch_bounds__(256, 2)
void expert_gemm_kernel(const float* __restrict__ x,
                        const float* __restrict__ eW,
                        float* __restrict__ out)
{
    const int e    = blockIdx.z;
    const int n    = g_cnt[e];
    const int row0 = blockIdx.y * BM;
    if (row0 >= n) return;
    const int col0 = blockIdx.x * BN;

    __shared__ int   stok[BM];
    __shared__ float swt[BM];

    const int tid  = threadIdx.x;
    const int lane = tid & 31;
    const int wid  = tid >> 5;
    const int wm   = wid & 1;        // 0..1 : M group (64 rows)
    const int wn   = wid >> 1;       // 0..3 : N group (32 cols)
    const int g    = lane >> 2;      // 0..7
    const int cq   = lane & 3;       // 0..3

    if (tid < BM) {
        const int r = row0 + tid;
        if (r < n) { stok[tid] = g_tok[e][r]; swt[tid] = g_wt[e][r]; }
        else       { stok[tid] = -1;          swt[tid] = 0.0f; }
    }
    __syncthreads();

    // A-load mapping: 128 rows x 8 float4; 2 threads/row, 4 float4 each
    const int ar = tid >> 1;             // row 0..127
    const int aj = (tid & 1) * 16;       // float offset within 32-wide k chunk
    const int atok = stok[ar];
    const float* xrow = x + (size_t)(atok < 0 ? 0 : atok) * DDIM;

    // B-load mapping: 32 k-rows x 32 float4; 8 threads/row, 4 float4 each
    const int bk = tid >> 3;             // k row 0..31
    const int bq = tid & 7;              // float4 group base
    const float* We = eW + (size_t)e * DDIM * DDIM;

    float c[4][4][4];                    // [mtile][ntile][frag]
#pragma unroll
    for (int mt = 0; mt < 4; mt++)
#pragma unroll
        for (int nt = 0; nt < 4; nt++)
#pragma unroll
            for (int i = 0; i < 4; i++) c[mt][nt][i] = 0.0f;

    float4 aR[4], bR[4];                 // in-flight global prefetch

    auto ldg_tile = [&](int t) {
        const float* as = xrow + t * BK + aj;
#pragma unroll
        for (int i = 0; i < 4; i++)
            aR[i] = *reinterpret_cast<const float4*>(as + i * 4);
        const float* bs = We + (size_t)(t * BK + bk) * DDIM + col0;
#pragma unroll
        for (int s = 0; s < 4; s++)
            bR[s] = *reinterpret_cast<const float4*>(bs + (bq + s * 8) * 4);
    };

    auto sts_tile = [&](int buf) {
        uint32_t* As = smu + buf * STAGEW;
        uint32_t* Bs = As + AWORDS;
#pragma unroll
        for (int i = 0; i < 4; i++) {
            uint4 u;
            u.x = f2tf32(aR[i].x); u.y = f2tf32(aR[i].y);
            u.z = f2tf32(aR[i].z); u.w = f2tf32(aR[i].w);
            *reinterpret_cast<uint4*>(&As[ar * ASTRIDE + aj + i * 4]) = u;
        }
#pragma unroll
        for (int s = 0; s < 4; s++) {
            uint4 u;
            u.x = f2tf32(bR[s].x); u.y = f2tf32(bR[s].y);
            u.z = f2tf32(bR[s].z); u.w = f2tf32(bR[s].w);
            *reinterpret_cast<uint4*>(&Bs[bk * BSTRIDE + (bq + s * 8) * 4]) = u;
        }
    };

    ldg_tile(0);
    sts_tile(0);
    __syncthreads();

    const int NT = DDIM / BK;            // 32
    for (int i = 0; i < NT; i++) {
        if (i + 1 < NT) ldg_tile(i + 1); // LDG issues early, lands during compute

        const uint32_t* As = smu + (i & 1) * STAGEW;
        const uint32_t* Bs = As + AWORDS;

#pragma unroll
        for (int kb = 0; kb < 4; kb++) {
            const int kk = kb * 8;
            uint32_t af[4][4];           // [mtile][frag]
#pragma unroll
            for (int mt = 0; mt < 4; mt++) {
                const int m = wm * 64 + mt * 16 + g;
                af[mt][0] = As[ m      * ASTRIDE + kk + cq];
                af[mt][1] = As[(m + 8) * ASTRIDE + kk + cq];
                af[mt][2] = As[ m      * ASTRIDE + kk + cq + 4];
                af[mt][3] = As[(m + 8) * ASTRIDE + kk + cq + 4];
            }
            uint32_t bf[4][2];           // [ntile][frag]
#pragma unroll
            for (int nt = 0; nt < 4; nt++) {
                const int nn = wn * 32 + nt * 8 + g;
                bf[nt][0] = Bs[(kk + cq)     * BSTRIDE + nn];
                bf[nt][1] = Bs[(kk + cq + 4) * BSTRIDE + nn];
            }
#pragma unroll
            for (int mt = 0; mt < 4; mt++)
#pragma unroll
                for (int nt = 0; nt < 4; nt++)
                    mma_tf32(c[mt][nt][0], c[mt][nt][1], c[mt][nt][2], c[mt][nt][3],
                             af[mt][0], af[mt][1], af[mt][2], af[mt][3],
                             bf[nt][0], bf[nt][1]);
        }

        if (i + 1 < NT) sts_tile((i + 1) & 1);  // opposite parity: race-free
        __syncthreads();                         // ONE barrier per K-tile
    }

    // epilogue: scale by routing weight, atomic-accumulate into out
#pragma unroll
    for (int mt = 0; mt < 4; mt++) {
#pragma unroll
        for (int half = 0; half < 2; half++) {
            const int lr  = wm * 64 + mt * 16 + g + half * 8;
            const int tok = stok[lr];
            if (tok < 0) continue;
            const float w = swt[lr];
            float* ob = out + (size_t)tok * DDIM + col0 + wn * 32 + cq * 2;
#pragma unroll
            for (int nt = 0; nt < 4; nt++) {
                atomicAdd(ob + nt * 8 + 0, w * c[mt][nt][half * 2 + 0]);
                atomicAdd(ob + nt * 8 + 1, w * c[mt][nt][half * 2 + 1]);
            }
        }
    }
}

// ---------------------------------------------------------------------------
extern "C" void kernel_launch(void* const* d_in, const int* in_sizes, int n_in,
                              void* d_out, int out_size)
{
    const float* x  = (const float*)d_in[0];   // [4,2048,1024]
    const float* gW = (const float*)d_in[1];   // [1024,8]
    const float* gb = (const float*)d_in[2];   // [8]
    const float* eW = (const float*)d_in[3];   // [8,1024,1024]
    const float* eb = (const float*)d_in[4];   // [8,1024]
    float* out = (float*)d_out;                // [4,2048,1024]

    cudaFuncSetAttribute(expert_gemm_kernel,
                         cudaFuncAttributeMaxDynamicSharedMemorySize, GEMM_SMEM);

    zero_counts_kernel<<<1, 32>>>();
    gating_kernel<<<NTOK / 8, 256>>>(x, gW, gb, eb, out);
    dim3 grid(DDIM / BN, NTOK / BM, NEXP);     // (8, 64, 8); y-tiles beyond n exit
    expert_gemm_kernel<<<grid, 256, GEMM_SMEM>>>(x, eW, out);
}

// round 11
// speedup vs baseline: 1.9235x; 1.1056x over previous
#include <cuda_runtime.h>
#include <cstdint>

// Problem constants
#define NTOK 8192        // B*S
#define DDIM 1024
#define NEXP 8
#define EPSV 1e-4f
#define WTHR 0.1f

// Scratch (device globals)
__device__ int   g_cnt[NEXP];
__device__ int   g_tok[NEXP][NTOK];
__device__ float g_wt [NEXP][NTOK];

// ---------------------------------------------------------------------------
__global__ void zero_counts_kernel() {
    if (threadIdx.x < NEXP) g_cnt[threadIdx.x] = 0;
}

// ---------------------------------------------------------------------------
// Gating + bias epilogue, fused. One warp per token. gate_W cached in smem.
// (Unchanged from the passing 321us version.)
// ---------------------------------------------------------------------------
__global__ __launch_bounds__(256)
void gating_kernel(const float* __restrict__ x,
                   const float* __restrict__ gW,
                   const float* __restrict__ gb,
                   const float* __restrict__ eb,
                   float* __restrict__ out)
{
    __shared__ float4 sgw[DDIM * 2];              // [D][E] as 2 float4/row, 32KB
    const int tid  = threadIdx.x;
    const int lane = tid & 31;

    const float4* gW4 = reinterpret_cast<const float4*>(gW);
    for (int i = tid; i < DDIM * 2; i += 256) sgw[i] = gW4[i];
    __syncthreads();

    const int warp = blockIdx.x * 8 + (tid >> 5);
    const float* xr = x + (size_t)warp * DDIM;

    float acc[NEXP];
#pragma unroll
    for (int e = 0; e < NEXP; e++) acc[e] = 0.0f;

#pragma unroll 4
    for (int d = lane; d < DDIM; d += 32) {
        const float xv = __ldg(xr + d);
        const float4 ga = sgw[d * 2 + 0];
        const float4 gc = sgw[d * 2 + 1];
        acc[0] = fmaf(xv, ga.x, acc[0]);
        acc[1] = fmaf(xv, ga.y, acc[1]);
        acc[2] = fmaf(xv, ga.z, acc[2]);
        acc[3] = fmaf(xv, ga.w, acc[3]);
        acc[4] = fmaf(xv, gc.x, acc[4]);
        acc[5] = fmaf(xv, gc.y, acc[5]);
        acc[6] = fmaf(xv, gc.z, acc[6]);
        acc[7] = fmaf(xv, gc.w, acc[7]);
    }
#pragma unroll
    for (int e = 0; e < NEXP; e++) {
#pragma unroll
        for (int off = 16; off > 0; off >>= 1)
            acc[e] += __shfl_xor_sync(0xffffffffu, acc[e], off);
    }

    int   i0 = 0, i1 = 0;
    float w0 = 0.f, w1 = 0.f;
    if (lane == 0) {
        float s[NEXP], p[NEXP];
        float mx = -1e30f;
#pragma unroll
        for (int e = 0; e < NEXP; e++) {
            s[e] = fmaxf(acc[e] + gb[e], EPSV);   // TEMP = 1.0
            mx = fmaxf(mx, s[e]);
        }
        float Z = 0.0f;
#pragma unroll
        for (int e = 0; e < NEXP; e++) { p[e] = expf(s[e] - mx); Z += p[e]; }
        const float invZ = 1.0f / Z;
#pragma unroll
        for (int e = 0; e < NEXP; e++) p[e] *= invZ;

        // top-2, strict '>' => lowest index wins ties (JAX semantics)
#pragma unroll
        for (int e = 1; e < NEXP; e++) if (p[e] > p[i0]) i0 = e;
        float best = -1e30f;
#pragma unroll
        for (int e = 0; e < NEXP; e++)
            if (e != i0 && p[e] > best) { best = p[e]; i1 = e; }

        w0 = fmaxf(p[i0], WTHR);
        w1 = fmaxf(p[i1], WTHR);
        const float sc = 0.5f / (w0 + w1);        // includes /K
        w0 *= sc; w1 *= sc;

        int s0 = atomicAdd(&g_cnt[i0], 1);
        g_tok[i0][s0] = warp;  g_wt[i0][s0] = w0;
        int s1 = atomicAdd(&g_cnt[i1], 1);
        g_tok[i1][s1] = warp;  g_wt[i1][s1] = w1;
    }
    // broadcast routing, write bias row (initializes every out element)
    i0 = __shfl_sync(0xffffffffu, i0, 0);
    i1 = __shfl_sync(0xffffffffu, i1, 0);
    w0 = __shfl_sync(0xffffffffu, w0, 0);
    w1 = __shfl_sync(0xffffffffu, w1, 0);

    const float4* b0 = reinterpret_cast<const float4*>(eb + i0 * DDIM);
    const float4* b1 = reinterpret_cast<const float4*>(eb + i1 * DDIM);
    float4* o4 = reinterpret_cast<float4*>(out + (size_t)warp * DDIM);
#pragma unroll
    for (int j = lane; j < DDIM / 4; j += 32) {
        const float4 u = __ldg(b0 + j);
        const float4 v = __ldg(b1 + j);
        float4 r;
        r.x = w0 * u.x + w1 * v.x;
        r.y = w0 * u.y + w1 * v.y;
        r.z = w0 * u.z + w1 * v.z;
        r.w = w0 * u.w + w1 * v.w;
        o4[j] = r;
    }
}

// ---------------------------------------------------------------------------
// tf32 tensor-core grouped GEMM.
// CTA 128x128x32, 8 warps (2 M x 4 N), warp tile 64x32 via m16n8k8.
// cp.async 3-stage ring (raw fp32 in smem), ONE __syncthreads per K-tile.
// tf32 rounding done on the fragment path as integer +0x1000 (== cvt.rna,
// since HMMA.TF32 ignores the low 13 mantissa bits).
// ---------------------------------------------------------------------------
#define BM 128
#define BN 128
#define BK 32
#define ASTRIDE 36                 // bank = 4m + k : conflict-free frag loads
#define BSTRIDE 136                // bank = 8k + n : conflict-free frag loads
#define AWORDS (BM * ASTRIDE)      // 4608
#define BWORDS (BK * BSTRIDE)      // 4352
#define STAGEW (AWORDS + BWORDS)   // 8960 words/stage
#define NSTAGE 3
#define GEMM_SMEM (NSTAGE * STAGEW * 4)   // 107520 B

extern __shared__ uint32_t smu[];

__device__ __forceinline__ void cp16(uint32_t dst, const float* src) {
    asm volatile("cp.async.cg.shared.global [%0], [%1], 16;"
                 :: "r"(dst), "l"(src));
}

// tf32 round-to-nearest-away == add half-ulp(2^12) to the raw fp32 bits;
// tensor core reads only the top 19 bits. Bit-identical to cvt.rna.tf32.
__device__ __forceinline__ uint32_t rnd(uint32_t u) { return u + 0x1000u; }

__device__ __forceinline__ void mma_tf32(float& d0, float& d1, float& d2, float& d3,
                                         uint32_t a0, uint32_t a1, uint32_t a2, uint32_t a3,
                                         uint32_t b0, uint32_t b1)
{
    asm volatile(
        "mma.sync.aligned.m16n8k8.row.col.f32.tf32.tf32.f32 "
        "{%0,%1,%2,%3}, {%4,%5,%6,%7}, {%8,%9}, {%0,%1,%2,%3};"
        : "+f"(d0), "+f"(d1), "+f"(d2), "+f"(d3)
        : "r"(a0), "r"(a1), "r"(a2), "r"(a3), "r"(b0), "r"(b1));
}

__global__ __launch_bounds__(256, 2)
void expert_gemm_kernel(const float* __restrict__ x,
                        const float* __restrict__ eW,
                        float* __restrict__ out)
{
    const int e    = blockIdx.z;
    const int n    = g_cnt[e];
    const int row0 = blockIdx.y * BM;
    if (row0 >= n) return;
    const int col0 = blockIdx.x * BN;

    __shared__ int   stok[BM];
    __shared__ float swt[BM];

    const int tid  = threadIdx.x;
    const int lane = tid & 31;
    const int wid  = tid >> 5;
    const int wm   = wid & 1;        // 0..1 : M group (64 rows)
    const int wn   = wid >> 1;       // 0..3 : N group (32 cols)
    const int g    = lane >> 2;      // 0..7
    const int cq   = lane & 3;       // 0..3

    if (tid < BM) {
        const int r = row0 + tid;
        if (r < n) { stok[tid] = g_tok[e][r]; swt[tid] = g_wt[e][r]; }
        else       { stok[tid] = -1;          swt[tid] = 0.0f; }
    }
    __syncthreads();

    // cp.async A mapping: 128 rows x 8 16B-chunks; 2 threads/row, 4 chunks each
    const int ar = tid >> 1;                 // row 0..127
    const int ac = (tid & 1) * 4;            // chunk base (chunks of 4 floats)
    const int atok = stok[ar];
    const float* asrc = x + (size_t)(atok < 0 ? 0 : atok) * DDIM + ac * 4;

    // cp.async B mapping: 32 k-rows x 32 16B-chunks; 8 threads/row, 4 chunks each
    const int bk = tid >> 3;                 // k-row 0..31
    const int bc = tid & 7;
    const float* We   = eW + (size_t)e * DDIM * DDIM;
    const float* bsrc = We + (size_t)bk * DDIM + col0 + bc * 4;

    const uint32_t smbase = (uint32_t)__cvta_generic_to_shared(smu);
    const uint32_t abase  = smbase + (ar * ASTRIDE + ac * 4) * 4;
    const uint32_t bbase  = smbase + (AWORDS + bk * BSTRIDE + bc * 4) * 4;

    float c[4][4][4];                        // [mtile][ntile][frag]
#pragma unroll
    for (int mt = 0; mt < 4; mt++)
#pragma unroll
        for (int nt = 0; nt < 4; nt++)
#pragma unroll
            for (int i = 0; i < 4; i++) c[mt][nt][i] = 0.0f;

    auto ldgsts = [&](int t, int stg) {
        const uint32_t off = (uint32_t)stg * (STAGEW * 4);
        const float* as = asrc + t * BK;
#pragma unroll
        for (int j = 0; j < 4; j++)
            cp16(abase + off + j * 16, as + j * 4);
        const float* bs = bsrc + (size_t)t * BK * DDIM;
#pragma unroll
        for (int s = 0; s < 4; s++)
            cp16(bbase + off + s * 128, bs + s * 32);
    };

    ldgsts(0, 0);
    asm volatile("cp.async.commit_group;");
    ldgsts(1, 1);
    asm volatile("cp.async.commit_group;");

    // fragment address bases (all further offsets are immediates)
    const uint32_t* Abase0 = smu + (wm * 64 + g) * ASTRIDE + cq;
    const uint32_t* Bbase0 = smu + AWORDS + cq * BSTRIDE + wn * 32 + g;

    const int NT = DDIM / BK;                // 32
    int stg = 0;                             // i % 3
    int stg2 = 2;                            // (i+2) % 3
    for (int i = 0; i < NT; i++) {
        asm volatile("cp.async.wait_group 1;");
        __syncthreads();                     // tile i visible to all warps

        const uint32_t* As = Abase0 + stg * STAGEW;
        const uint32_t* Bs = Bbase0 + stg * STAGEW;

#pragma unroll
        for (int kb = 0; kb < 4; kb++) {
            const int kk = kb * 8;
            uint32_t af[4][4];               // [mtile][frag]
#pragma unroll
            for (int mt = 0; mt < 4; mt++) {
                const uint32_t* Am = As + mt * (16 * ASTRIDE);
                af[mt][0] = rnd(Am[kk]);
                af[mt][1] = rnd(Am[8 * ASTRIDE + kk]);
                af[mt][2] = rnd(Am[kk + 4]);
                af[mt][3] = rnd(Am[8 * ASTRIDE + kk + 4]);
            }
            uint32_t bf[4][2];               // [ntile][frag]
#pragma unroll
            for (int nt = 0; nt < 4; nt++) {
                bf[nt][0] = rnd(Bs[kk * BSTRIDE + nt * 8]);
                bf[nt][1] = rnd(Bs[(kk + 4) * BSTRIDE + nt * 8]);
            }
#pragma unroll
            for (int mt = 0; mt < 4; mt++)
#pragma unroll
                for (int nt = 0; nt < 4; nt++)
                    mma_tf32(c[mt][nt][0], c[mt][nt][1], c[mt][nt][2], c[mt][nt][3],
                             af[mt][0], af[mt][1], af[mt][2], af[mt][3],
                             bf[nt][0], bf[nt][1]);
        }

        if (i + 2 < NT) ldgsts(i + 2, stg2); // overwrites buf(i-1): safe, all
                                             // warps passed this iter's barrier
        asm volatile("cp.async.commit_group;");

        stg  = (stg  == 2) ? 0 : stg  + 1;
        stg2 = (stg2 == 2) ? 0 : stg2 + 1;
    }

    // epilogue: scale by routing weight, atomic-accumulate into out
#pragma unroll
    for (int mt = 0; mt < 4; mt++) {
#pragma unroll
        for (int half = 0; half < 2; half++) {
            const int lr  = wm * 64 + mt * 16 + g + half * 8;
            const int tok = stok[lr];
            if (tok < 0) continue;
            const float w = swt[lr];
            float* ob = out + (size_t)tok * DDIM + col0 + wn * 32 + cq * 2;
#pragma unroll
            for (int nt = 0; nt < 4; nt++) {
                atomicAdd(ob + nt * 8 + 0, w * c[mt][nt][half * 2 + 0]);
                atomicAdd(ob + nt * 8 + 1, w * c[mt][nt][half * 2 + 1]);
            }
        }
    }
}

// ---------------------------------------------------------------------------
extern "C" void kernel_launch(void* const* d_in, const int* in_sizes, int n_in,
                              void* d_out, int out_size)
{
    const float* x  = (const float*)d_in[0];   // [4,2048,1024]
    const float* gW = (const float*)d_in[1];   // [1024,8]
    const float* gb = (const float*)d_in[2];   // [8]
    const float* eW = (const float*)d_in[3];   // [8,1024,1024]
    const float* eb = (const float*)d_in[4];   // [8,1024]
    float* out = (float*)d_out;                // [4,2048,1024]

    cudaFuncSetAttribute(expert_gemm_kernel,
                         cudaFuncAttributeMaxDynamicSharedMemorySize, GEMM_SMEM);

    zero_counts_kernel<<<1, 32>>>();
    gating_kernel<<<NTOK / 8, 256>>>(x, gW, gb, eb, out);
    dim3 grid(DDIM / BN, NTOK / BM, NEXP);     // (8, 64, 8); y-tiles beyond n exit
    expert_gemm_kernel<<<grid, 256, GEMM_SMEM>>>(x, eW, out);
}

// round 13
// speedup vs baseline: 2.0838x; 1.0833x over previous
#include <cuda_runtime.h>
#include <cstdint>

// Problem constants
#define NTOK 8192        // B*S
#define DDIM 1024
#define NEXP 8
#define EPSV 1e-4f
#define WTHR 0.1f

// Scratch (device globals)
__device__ int   g_cnt[NEXP];
__device__ int   g_tok[NEXP][NTOK];
__device__ float g_wt [NEXP][NTOK];
__device__ float g_xr [NTOK * DDIM];           // tf32-rounded, k-pair-permuted x
__device__ float g_wr [NEXP * DDIM * DDIM];    // tf32-rounded W (same layout)

// tf32 round-to-nearest-away with low 13 bits cleared.
// Bit-identical (after HMMA truncation) to the in-loop +0x1000 trick that
// produced rel_err 2.935178e-4 in rounds 8-11.
__device__ __forceinline__ float tf32r(float f) {
    uint32_t u = __float_as_uint(f);
    u = (u + 0x1000u) & 0xFFFFE000u;
    return __uint_as_float(u);
}

// ---------------------------------------------------------------------------
// Pre-pass 1: round + k-pair-permute x -> g_xr. Each thread owns one 8-float
// k-block: out position 2*cq+h  <-  in position cq + 4*h  (cq<4, h<2).
// Block 0 also zeroes the per-expert counters.
// ---------------------------------------------------------------------------
__global__ void round_x_kernel(const float* __restrict__ x) {
    if (blockIdx.x == 0 && threadIdx.x < NEXP) g_cnt[threadIdx.x] = 0;
    const int i = blockIdx.x * 256 + threadIdx.x;       // 8-float block index
    const float4 v0 = reinterpret_cast<const float4*>(x)[i * 2 + 0];
    const float4 v1 = reinterpret_cast<const float4*>(x)[i * 2 + 1];
    float4 o0, o1;
    o0.x = tf32r(v0.x); o0.y = tf32r(v1.x);   // k0, k4
    o0.z = tf32r(v0.y); o0.w = tf32r(v1.y);   // k1, k5
    o1.x = tf32r(v0.z); o1.y = tf32r(v1.z);   // k2, k6
    o1.z = tf32r(v0.w); o1.w = tf32r(v1.w);   // k3, k7
    reinterpret_cast<float4*>(g_xr)[i * 2 + 0] = o0;
    reinterpret_cast<float4*>(g_xr)[i * 2 + 1] = o1;
}

// ---------------------------------------------------------------------------
// Pre-pass 2: round W elementwise (layout unchanged, [e][k][n]).
// ---------------------------------------------------------------------------
__global__ void round_w_kernel(const float* __restrict__ eW) {
    const int i = blockIdx.x * 256 + threadIdx.x;       // float4 index
    const float4 v = reinterpret_cast<const float4*>(eW)[i];
    float4 r;
    r.x = tf32r(v.x); r.y = tf32r(v.y); r.z = tf32r(v.z); r.w = tf32r(v.w);
    reinterpret_cast<float4*>(g_wr)[i] = r;
}

// ---------------------------------------------------------------------------
// Gating + bias epilogue, fused (unchanged from passing 290us version).
// ---------------------------------------------------------------------------
__global__ __launch_bounds__(256)
void gating_kernel(const float* __restrict__ x,
                   const float* __restrict__ gW,
                   const float* __restrict__ gb,
                   const float* __restrict__ eb,
                   float* __restrict__ out)
{
    __shared__ float4 sgw[DDIM * 2];
    const int tid  = threadIdx.x;
    const int lane = tid & 31;

    const float4* gW4 = reinterpret_cast<const float4*>(gW);
    for (int i = tid; i < DDIM * 2; i += 256) sgw[i] = gW4[i];
    __syncthreads();

    const int warp = blockIdx.x * 8 + (tid >> 5);
    const float* xr = x + (size_t)warp * DDIM;

    float acc[NEXP];
#pragma unroll
    for (int e = 0; e < NEXP; e++) acc[e] = 0.0f;

#pragma unroll 4
    for (int d = lane; d < DDIM; d += 32) {
        const float xv = __ldg(xr + d);
        const float4 ga = sgw[d * 2 + 0];
        const float4 gc = sgw[d * 2 + 1];
        acc[0] = fmaf(xv, ga.x, acc[0]);
        acc[1] = fmaf(xv, ga.y, acc[1]);
        acc[2] = fmaf(xv, ga.z, acc[2]);
        acc[3] = fmaf(xv, ga.w, acc[3]);
        acc[4] = fmaf(xv, gc.x, acc[4]);
        acc[5] = fmaf(xv, gc.y, acc[5]);
        acc[6] = fmaf(xv, gc.z, acc[6]);
        acc[7] = fmaf(xv, gc.w, acc[7]);
    }
#pragma unroll
    for (int e = 0; e < NEXP; e++) {
#pragma unroll
        for (int off = 16; off > 0; off >>= 1)
            acc[e] += __shfl_xor_sync(0xffffffffu, acc[e], off);
    }

    int   i0 = 0, i1 = 0;
    float w0 = 0.f, w1 = 0.f;
    if (lane == 0) {
        float s[NEXP], p[NEXP];
        float mx = -1e30f;
#pragma unroll
        for (int e = 0; e < NEXP; e++) {
            s[e] = fmaxf(acc[e] + gb[e], EPSV);   // TEMP = 1.0
            mx = fmaxf(mx, s[e]);
        }
        float Z = 0.0f;
#pragma unroll
        for (int e = 0; e < NEXP; e++) { p[e] = expf(s[e] - mx); Z += p[e]; }
        const float invZ = 1.0f / Z;
#pragma unroll
        for (int e = 0; e < NEXP; e++) p[e] *= invZ;

        // top-2, strict '>' => lowest index wins ties (JAX semantics)
#pragma unroll
        for (int e = 1; e < NEXP; e++) if (p[e] > p[i0]) i0 = e;
        float best = -1e30f;
#pragma unroll
        for (int e = 0; e < NEXP; e++)
            if (e != i0 && p[e] > best) { best = p[e]; i1 = e; }

        w0 = fmaxf(p[i0], WTHR);
        w1 = fmaxf(p[i1], WTHR);
        const float sc = 0.5f / (w0 + w1);        // includes /K
        w0 *= sc; w1 *= sc;

        int s0 = atomicAdd(&g_cnt[i0], 1);
        g_tok[i0][s0] = warp;  g_wt[i0][s0] = w0;
        int s1 = atomicAdd(&g_cnt[i1], 1);
        g_tok[i1][s1] = warp;  g_wt[i1][s1] = w1;
    }
    i0 = __shfl_sync(0xffffffffu, i0, 0);
    i1 = __shfl_sync(0xffffffffu, i1, 0);
    w0 = __shfl_sync(0xffffffffu, w0, 0);
    w1 = __shfl_sync(0xffffffffu, w1, 0);

    const float4* b0 = reinterpret_cast<const float4*>(eb + i0 * DDIM);
    const float4* b1 = reinterpret_cast<const float4*>(eb + i1 * DDIM);
    float4* o4 = reinterpret_cast<float4*>(out + (size_t)warp * DDIM);
#pragma unroll
    for (int j = lane; j < DDIM / 4; j += 32) {
        const float4 u = __ldg(b0 + j);
        const float4 v = __ldg(b1 + j);
        float4 r;
        r.x = w0 * u.x + w1 * v.x;
        r.y = w0 * u.y + w1 * v.y;
        r.z = w0 * u.z + w1 * v.z;
        r.w = w0 * u.w + w1 * v.w;
        o4[j] = r;
    }
}

// ---------------------------------------------------------------------------
// tf32 tensor-core grouped GEMM (round-11 pipeline, pre-rounded operands).
// CTA 128x128x32, 8 warps (2 M x 4 N), warp tile 64x32 via m16n8k8.
// cp.async 3-stage ring, ONE __syncthreads per K-tile.
// A smem: 128B rows, k-pair-permuted (from g_xr), 8B-unit XOR swizzle
//         -> fragment loads are conflict-free LDS.64 pairs.
// B smem: padded rows (BSTRIDE=136), conflict-free LDS.32 (round-11 proven).
// ---------------------------------------------------------------------------
#define BM 128
#define BN 128
#define BK 32
#define ABYTES (BM * BK * 4)        // 16384 : A stage bytes (stride 32 words)
#define BSTRIDE 136
#define BWORDS (BK * BSTRIDE)       // 4352
#define STAGEB (ABYTES + BWORDS * 4)   // 33792 bytes/stage
#define NSTAGE 3
#define GEMM_SMEM (NSTAGE * STAGEB)    // 101376 B

extern __shared__ uint32_t smu[];

__device__ __forceinline__ void cp16(uint32_t dst, const float* src) {
    asm volatile("cp.async.cg.shared.global [%0], [%1], 16;" :: "r"(dst), "l"(src));
}

__device__ __forceinline__ void mma_tf32(float& d0, float& d1, float& d2, float& d3,
                                         uint32_t a0, uint32_t a1, uint32_t a2, uint32_t a3,
                                         uint32_t b0, uint32_t b1)
{
    asm volatile(
        "mma.sync.aligned.m16n8k8.row.col.f32.tf32.tf32.f32 "
        "{%0,%1,%2,%3}, {%4,%5,%6,%7}, {%8,%9}, {%0,%1,%2,%3};"
        : "+f"(d0), "+f"(d1), "+f"(d2), "+f"(d3)
        : "r"(a0), "r"(a1), "r"(a2), "r"(a3), "r"(b0), "r"(b1));
}

__global__ __launch_bounds__(256, 2)
void expert_gemm_kernel(float* __restrict__ out)
{
    const int e    = blockIdx.z;
    const int n    = g_cnt[e];
    const int row0 = blockIdx.y * BM;
    if (row0 >= n) return;
    const int col0 = blockIdx.x * BN;

    __shared__ int   stok[BM];
    __shared__ float swt[BM];

    const int tid  = threadIdx.x;
    const int lane = tid & 31;
    const int wid  = tid >> 5;
    const int wm   = wid & 1;        // 0..1 : M group (64 rows)
    const int wn   = wid >> 1;       // 0..3 : N group (32 cols)
    const int g    = lane >> 2;      // 0..7
    const int cq   = lane & 3;       // 0..3

    if (tid < BM) {
        const int r = row0 + tid;
        if (r < n) { stok[tid] = g_tok[e][r]; swt[tid] = g_wt[e][r]; }
        else       { stok[tid] = -1;          swt[tid] = 0.0f; }
    }
    __syncthreads();

    // cp.async A mapping: 128 rows x 8 16B-chunks; 2 threads/row, 4 chunks each
    const int ar = tid >> 1;                 // row 0..127
    const int ac = (tid & 1) * 4;            // first chunk index (0 or 4)
    const int atok = stok[ar];
    const float* asrc = g_xr + (size_t)(atok < 0 ? 0 : atok) * DDIM + ac * 4;
    const uint32_t axm = (uint32_t)(ar & 3) << 2;   // store-side 8B-unit swizzle

    // cp.async B mapping: 32 k-rows x 32 16B-chunks; 8 threads/row, 4 chunks each
    const int bk = tid >> 3;                 // k-row 0..31
    const int bc = tid & 7;
    const float* bsrc = g_wr + ((size_t)e * DDIM + bk) * DDIM + col0 + bc * 4;

    const uint32_t smbase = (uint32_t)__cvta_generic_to_shared(smu);
    const uint32_t bbase  = smbase + ABYTES + (bk * BSTRIDE + bc * 4) * 4;

    float c[4][4][4];                        // [mtile][ntile][frag]
#pragma unroll
    for (int mt = 0; mt < 4; mt++)
#pragma unroll
        for (int nt = 0; nt < 4; nt++)
#pragma unroll
            for (int i = 0; i < 4; i++) c[mt][nt][i] = 0.0f;

    auto ldgsts = [&](int t, int stg) {
        const uint32_t off = (uint32_t)stg * STAGEB;
        const float* as = asrc + t * BK;
#pragma unroll
        for (int j = 0; j < 4; j++) {
            const uint32_t u = ((uint32_t)(2 * (ac + j)) ^ axm) * 8;  // swizzled bytes
            cp16(smbase + off + (uint32_t)ar * 128 + u, as + j * 4);
        }
        const float* bs = bsrc + (size_t)t * BK * DDIM;
#pragma unroll
        for (int s = 0; s < 4; s++)
            cp16(bbase + off + s * 128, bs + s * 32);
    };

    ldgsts(0, 0);
    asm volatile("cp.async.commit_group;");
    ldgsts(1, 1);
    asm volatile("cp.async.commit_group;");

    // fragment bases
    const char* Am0 = (const char*)smu + (wm * 64 + g) * 128;        // rows m
    const uint32_t* Bbase0 = smu + (ABYTES / 4) + cq * BSTRIDE + wn * 32 + g;
    const uint32_t fxm = (uint32_t)(g & 3) << 2;                     // load-side swizzle
    uint32_t offk[4];                        // per-kb swizzled 8B-unit byte offsets
#pragma unroll
    for (int kb = 0; kb < 4; kb++)
        offk[kb] = (((uint32_t)(kb * 4 + cq)) ^ fxm) * 8;

    const int NT = DDIM / BK;                // 32
    int stg = 0, stg2 = 2;
    for (int i = 0; i < NT; i++) {
        asm volatile("cp.async.wait_group 1;");
        __syncthreads();                     // tile i visible to all warps

        const char*     As = Am0 + stg * STAGEB;
        const uint32_t* Bs = Bbase0 + stg * (STAGEB / 4);

#pragma unroll
        for (int kb = 0; kb < 4; kb++) {
            const int kk = kb * 8;
            uint2 pa[4], pb[4];              // [mtile] : (k,k+4) pairs, rows m / m+8
#pragma unroll
            for (int mt = 0; mt < 4; mt++) {
                const char* r0 = As + mt * (16 * 128) + offk[kb];
                pa[mt] = *reinterpret_cast<const uint2*>(r0);
                pb[mt] = *reinterpret_cast<const uint2*>(r0 + 8 * 128);
            }
            uint32_t bf[4][2];               // [ntile][frag]
#pragma unroll
            for (int nt = 0; nt < 4; nt++) {
                bf[nt][0] = Bs[kk * BSTRIDE + nt * 8];
                bf[nt][1] = Bs[(kk + 4) * BSTRIDE + nt * 8];
            }
#pragma unroll
            for (int mt = 0; mt < 4; mt++)
#pragma unroll
                for (int nt = 0; nt < 4; nt++)
                    mma_tf32(c[mt][nt][0], c[mt][nt][1], c[mt][nt][2], c[mt][nt][3],
                             pa[mt].x, pb[mt].x, pa[mt].y, pb[mt].y,
                             bf[nt][0], bf[nt][1]);
        }

        if (i + 2 < NT) ldgsts(i + 2, stg2); // overwrites buf(i-1): safe post-barrier
        asm volatile("cp.async.commit_group;");

        stg  = (stg  == 2) ? 0 : stg  + 1;
        stg2 = (stg2 == 2) ? 0 : stg2 + 1;
    }

    // epilogue: scale by routing weight, atomic-accumulate into out
#pragma unroll
    for (int mt = 0; mt < 4; mt++) {
#pragma unroll
        for (int half = 0; half < 2; half++) {
            const int lr  = wm * 64 + mt * 16 + g + half * 8;
            const int tok = stok[lr];
            if (tok < 0) continue;
            const float w = swt[lr];
            float* ob = out + (size_t)tok * DDIM + col0 + wn * 32 + cq * 2;
#pragma unroll
            for (int nt = 0; nt < 4; nt++) {
                atomicAdd(ob + nt * 8 + 0, w * c[mt][nt][half * 2 + 0]);
                atomicAdd(ob + nt * 8 + 1, w * c[mt][nt][half * 2 + 1]);
            }
        }
    }
}

// ---------------------------------------------------------------------------
extern "C" void kernel_launch(void* const* d_in, const int* in_sizes, int n_in,
                              void* d_out, int out_size)
{
    const float* x  = (const float*)d_in[0];   // [4,2048,1024]
    const float* gW = (const float*)d_in[1];   // [1024,8]
    const float* gb = (const float*)d_in[2];   // [8]
    const float* eW = (const float*)d_in[3];   // [8,1024,1024]
    const float* eb = (const float*)d_in[4];   // [8,1024]
    float* out = (float*)d_out;                // [4,2048,1024]

    cudaFuncSetAttribute(expert_gemm_kernel,
                         cudaFuncAttributeMaxDynamicSharedMemorySize, GEMM_SMEM);

    round_x_kernel<<<NTOK * DDIM / 8 / 256, 256>>>(x);
    round_w_kernel<<<NEXP * DDIM * DDIM / 4 / 256, 256>>>(eW);
    gating_kernel<<<NTOK / 8, 256>>>(x, gW, gb, eb, out);
    dim3 grid(DDIM / BN, NTOK / BM, NEXP);     // (8, 64, 8); y-tiles beyond n exit
    expert_gemm_kernel<<<grid, 256, GEMM_SMEM>>>(out);
}

// round 14
// speedup vs baseline: 2.0848x; 1.0005x over previous
#include <cuda_runtime.h>
#include <cstdint>

// Problem constants
#define NTOK 8192        // B*S
#define DDIM 1024
#define NEXP 8
#define EPSV 1e-4f
#define WTHR 0.1f

// Scratch (device globals)
__device__ int   g_cnt[NEXP];
__device__ int   g_tok[NEXP][NTOK];
__device__ float g_wt [NEXP][NTOK];
__device__ float g_xr [NTOK * DDIM];           // tf32-rounded, k-pair-permuted x
__device__ float g_wp [NEXP * DDIM * DDIM];    // tf32-rounded, k-paired W
// g_wp layout: [e][r][2n+h], r = 4*(k>>3)+(k&3), h = (k>>2)&1  (k = 8*(r>>2)+(r&3)+4h)

// tf32 round-to-nearest-away with low 13 bits cleared (== cvt.rna.tf32 bits;
// produced rel_err 2.935178e-4 in rounds 8-13).
__device__ __forceinline__ float tf32r(float f) {
    uint32_t u = __float_as_uint(f);
    u = (u + 0x1000u) & 0xFFFFE000u;
    return __uint_as_float(u);
}

// ---------------------------------------------------------------------------
// Pre-pass: round + k-pair W -> g_wp. Block 0 also zeroes per-expert counters.
// Each thread emits one float4 = pairs (n, n+1) for one (e, r).
// ---------------------------------------------------------------------------
__global__ void pair_w_kernel(const float* __restrict__ eW) {
    if (blockIdx.x == 0 && threadIdx.x < NEXP) g_cnt[threadIdx.x] = 0;
    const int i   = blockIdx.x * 256 + threadIdx.x;   // float4 out index
    const int e   = i >> 18;                          // / (512*512)
    const int rem = i & 262143;
    const int r   = rem >> 9;                         // row 0..511
    const int j   = rem & 511;                        // float4 within row
    const int n   = j * 2;
    const int k0  = ((r >> 2) << 3) + (r & 3);        // k for h=0 ; k1 = k0+4
    const float2 a = *reinterpret_cast<const float2*>(
        eW + ((size_t)e * DDIM + k0) * DDIM + n);
    const float2 b = *reinterpret_cast<const float2*>(
        eW + ((size_t)e * DDIM + k0 + 4) * DDIM + n);
    float4 o;
    o.x = tf32r(a.x); o.y = tf32r(b.x); o.z = tf32r(a.y); o.w = tf32r(b.y);
    reinterpret_cast<float4*>(g_wp)[i] = o;
}

// ---------------------------------------------------------------------------
// Gating + bias epilogue + x rounding, fused. One warp per token.
// Routing math byte-identical to rounds 5-13 (passed).
// ---------------------------------------------------------------------------
__global__ __launch_bounds__(256)
void gating_kernel(const float* __restrict__ x,
                   const float* __restrict__ gW,
                   const float* __restrict__ gb,
                   const float* __restrict__ eb,
                   float* __restrict__ out)
{
    __shared__ float4 sgw[DDIM * 2];
    const int tid  = threadIdx.x;
    const int lane = tid & 31;

    const float4* gW4 = reinterpret_cast<const float4*>(gW);
    for (int i = tid; i < DDIM * 2; i += 256) sgw[i] = gW4[i];
    __syncthreads();

    const int warp = blockIdx.x * 8 + (tid >> 5);
    const float* xr = x + (size_t)warp * DDIM;
    float* xw = g_xr + (size_t)warp * DDIM;

    float acc[NEXP];
#pragma unroll
    for (int e = 0; e < NEXP; e++) acc[e] = 0.0f;

#pragma unroll 4
    for (int d = lane; d < DDIM; d += 32) {
        const float xv = __ldg(xr + d);
        // rounded + k-pair-permuted store for the GEMM A operand
        const int o = d & 7;
        xw[(d & ~7) + ((o & 3) << 1) + (o >> 2)] = tf32r(xv);
        const float4 ga = sgw[d * 2 + 0];
        const float4 gc = sgw[d * 2 + 1];
        acc[0] = fmaf(xv, ga.x, acc[0]);
        acc[1] = fmaf(xv, ga.y, acc[1]);
        acc[2] = fmaf(xv, ga.z, acc[2]);
        acc[3] = fmaf(xv, ga.w, acc[3]);
        acc[4] = fmaf(xv, gc.x, acc[4]);
        acc[5] = fmaf(xv, gc.y, acc[5]);
        acc[6] = fmaf(xv, gc.z, acc[6]);
        acc[7] = fmaf(xv, gc.w, acc[7]);
    }
#pragma unroll
    for (int e = 0; e < NEXP; e++) {
#pragma unroll
        for (int off = 16; off > 0; off >>= 1)
            acc[e] += __shfl_xor_sync(0xffffffffu, acc[e], off);
    }

    int   i0 = 0, i1 = 0;
    float w0 = 0.f, w1 = 0.f;
    if (lane == 0) {
        float s[NEXP], p[NEXP];
        float mx = -1e30f;
#pragma unroll
        for (int e = 0; e < NEXP; e++) {
            s[e] = fmaxf(acc[e] + gb[e], EPSV);   // TEMP = 1.0
            mx = fmaxf(mx, s[e]);
        }
        float Z = 0.0f;
#pragma unroll
        for (int e = 0; e < NEXP; e++) { p[e] = expf(s[e] - mx); Z += p[e]; }
        const float invZ = 1.0f / Z;
#pragma unroll
        for (int e = 0; e < NEXP; e++) p[e] *= invZ;

        // top-2, strict '>' => lowest index wins ties (JAX semantics)
#pragma unroll
        for (int e = 1; e < NEXP; e++) if (p[e] > p[i0]) i0 = e;
        float best = -1e30f;
#pragma unroll
        for (int e = 0; e < NEXP; e++)
            if (e != i0 && p[e] > best) { best = p[e]; i1 = e; }

        w0 = fmaxf(p[i0], WTHR);
        w1 = fmaxf(p[i1], WTHR);
        const float sc = 0.5f / (w0 + w1);        // includes /K
        w0 *= sc; w1 *= sc;

        int s0 = atomicAdd(&g_cnt[i0], 1);
        g_tok[i0][s0] = warp;  g_wt[i0][s0] = w0;
        int s1 = atomicAdd(&g_cnt[i1], 1);
        g_tok[i1][s1] = warp;  g_wt[i1][s1] = w1;
    }
    i0 = __shfl_sync(0xffffffffu, i0, 0);
    i1 = __shfl_sync(0xffffffffu, i1, 0);
    w0 = __shfl_sync(0xffffffffu, w0, 0);
    w1 = __shfl_sync(0xffffffffu, w1, 0);

    const float4* b0 = reinterpret_cast<const float4*>(eb + i0 * DDIM);
    const float4* b1 = reinterpret_cast<const float4*>(eb + i1 * DDIM);
    float4* o4 = reinterpret_cast<float4*>(out + (size_t)warp * DDIM);
#pragma unroll
    for (int j = lane; j < DDIM / 4; j += 32) {
        const float4 u = __ldg(b0 + j);
        const float4 v = __ldg(b1 + j);
        float4 r;
        r.x = w0 * u.x + w1 * v.x;
        r.y = w0 * u.y + w1 * v.y;
        r.z = w0 * u.z + w1 * v.z;
        r.w = w0 * u.w + w1 * v.w;
        o4[j] = r;
    }
}

// ---------------------------------------------------------------------------
// tf32 tensor-core grouped GEMM (round-13 pipeline; BOTH operands k-paired
// -> all fragment loads are conflict-free LDS.64).
// CTA 128x128x32, 8 warps (2 M x 4 N), warp tile 64x32 via m16n8k8.
// cp.async 3-stage ring, ONE __syncthreads per K-tile.
// A smem: 128 rows x 128B, 8B-unit swizzle u^((m&3)<<2).
// B smem: 16 rows x 1024B (k-paired), 8B-unit swizzle u^((row&3)<<2).
// ---------------------------------------------------------------------------
#define BM 128
#define BN 128
#define BK 32
#define ABYTES (BM * BK * 4)        // 16384
#define BBYTES (BN * BK * 4)        // 16384 (k-paired, unpadded)
#define STAGEB (ABYTES + BBYTES)    // 32768 bytes/stage
#define NSTAGE 3
#define GEMM_SMEM (NSTAGE * STAGEB) // 98304 B

extern __shared__ uint32_t smu[];

__device__ __forceinline__ void cp16(uint32_t dst, const float* src) {
    asm volatile("cp.async.cg.shared.global [%0], [%1], 16;" :: "r"(dst), "l"(src));
}

__device__ __forceinline__ void mma_tf32(float& d0, float& d1, float& d2, float& d3,
                                         uint32_t a0, uint32_t a1, uint32_t a2, uint32_t a3,
                                         uint32_t b0, uint32_t b1)
{
    asm volatile(
        "mma.sync.aligned.m16n8k8.row.col.f32.tf32.tf32.f32 "
        "{%0,%1,%2,%3}, {%4,%5,%6,%7}, {%8,%9}, {%0,%1,%2,%3};"
        : "+f"(d0), "+f"(d1), "+f"(d2), "+f"(d3)
        : "r"(a0), "r"(a1), "r"(a2), "r"(a3), "r"(b0), "r"(b1));
}

__global__ __launch_bounds__(256, 2)
void expert_gemm_kernel(float* __restrict__ out)
{
    const int e    = blockIdx.z;
    const int n    = g_cnt[e];
    const int row0 = blockIdx.y * BM;
    if (row0 >= n) return;
    const int col0 = blockIdx.x * BN;

    __shared__ int   stok[BM];
    __shared__ float swt[BM];

    const int tid  = threadIdx.x;
    const int lane = tid & 31;
    const int wid  = tid >> 5;
    const int wm   = wid & 1;        // 0..1 : M group (64 rows)
    const int wn   = wid >> 1;       // 0..3 : N group (32 cols)
    const int g    = lane >> 2;      // 0..7
    const int cq   = lane & 3;       // 0..3

    if (tid < BM) {
        const int r = row0 + tid;
        if (r < n) { stok[tid] = g_tok[e][r]; swt[tid] = g_wt[e][r]; }
        else       { stok[tid] = -1;          swt[tid] = 0.0f; }
    }
    __syncthreads();

    // cp.async A mapping: 128 rows x 8 16B-chunks; 2 threads/row, 4 chunks each
    const int ar = tid >> 1;                 // row 0..127
    const int ac = (tid & 1) * 4;            // first chunk (0 or 4)
    const int atok = stok[ar];
    const float* asrc = g_xr + (size_t)(atok < 0 ? 0 : atok) * DDIM + ac * 4;
    const uint32_t axm = (uint32_t)(ar & 3) << 2;   // A store-side 8B-unit swizzle

    // cp.async B mapping: 16 paired rows x 64 16B-chunks; 16 threads/row, 4 each
    const int blr = tid >> 4;                // local row 0..15
    const int bj  = tid & 15;                // chunk base
    const float* bsrc = g_wp + ((size_t)e * 512 + blr) * 2048 + col0 * 2 + bj * 4;
    const uint32_t bxm = (uint32_t)(blr & 3) << 2;  // B store-side swizzle

    const uint32_t smbase = (uint32_t)__cvta_generic_to_shared(smu);

    float c[4][4][4];                        // [mtile][ntile][frag]
#pragma unroll
    for (int mt = 0; mt < 4; mt++)
#pragma unroll
        for (int nt = 0; nt < 4; nt++)
#pragma unroll
            for (int i = 0; i < 4; i++) c[mt][nt][i] = 0.0f;

    auto ldgsts = [&](int t, int stg) {
        const uint32_t off = (uint32_t)stg * STAGEB;
        const float* as = asrc + t * BK;
#pragma unroll
        for (int j = 0; j < 4; j++) {
            const uint32_t u = ((uint32_t)(2 * (ac + j)) ^ axm) * 8;
            cp16(smbase + off + (uint32_t)ar * 128 + u, as + j * 4);
        }
        const float* bs = bsrc + (size_t)t * (16 * 2048);   // 16 rows per tile
#pragma unroll
        for (int s = 0; s < 4; s++) {
            const uint32_t u = ((uint32_t)(2 * (bj + 16 * s)) ^ bxm) * 8;
            cp16(smbase + off + ABYTES + (uint32_t)blr * 1024 + u, bs + s * 64);
        }
    };

    ldgsts(0, 0);
    asm volatile("cp.async.commit_group;");
    ldgsts(1, 1);
    asm volatile("cp.async.commit_group;");

    // fragment bases
    const char* Am0 = (const char*)smu + (wm * 64 + g) * 128;
    const char* Bm0 = (const char*)smu + ABYTES + cq * 1024 + wn * 256;
    const uint32_t fxm = (uint32_t)(g & 3) << 2;    // A load-side swizzle
    const uint32_t bfm = (uint32_t)cq << 2;         // B load-side swizzle
    uint32_t offk[4];                               // A per-kb swizzled offsets
#pragma unroll
    for (int kb = 0; kb < 4; kb++)
        offk[kb] = (((uint32_t)(kb * 4 + cq)) ^ fxm) * 8;
    uint32_t boff[4][4];                            // B per-(kb,nt) offsets
#pragma unroll
    for (int kb = 0; kb < 4; kb++)
#pragma unroll
        for (int nt = 0; nt < 4; nt++)
            boff[kb][nt] = (uint32_t)kb * 4096 +
                           (((uint32_t)(nt * 8 + g)) ^ bfm) * 8;

    const int NT = DDIM / BK;                // 32
    int stg = 0, stg2 = 2;
    for (int i = 0; i < NT; i++) {
        asm volatile("cp.async.wait_group 1;");
        __syncthreads();                     // tile i visible to all warps

        const char* As = Am0 + stg * STAGEB;
        const char* Bs = Bm0 + stg * STAGEB;

#pragma unroll
        for (int kb = 0; kb < 4; kb++) {
            uint2 pa[4], pb[4];              // [mtile] : (k,k+4) pairs, rows m / m+8
#pragma unroll
            for (int mt = 0; mt < 4; mt++) {
                const char* r0 = As + mt * (16 * 128) + offk[kb];
                pa[mt] = *reinterpret_cast<const uint2*>(r0);
                pb[mt] = *reinterpret_cast<const uint2*>(r0 + 8 * 128);
            }
            uint2 bp[4];                     // [ntile] : (k,k+4) pairs
#pragma unroll
            for (int nt = 0; nt < 4; nt++)
                bp[nt] = *reinterpret_cast<const uint2*>(Bs + boff[kb][nt]);
#pragma unroll
            for (int mt = 0; mt < 4; mt++)
#pragma unroll
                for (int nt = 0; nt < 4; nt++)
                    mma_tf32(c[mt][nt][0], c[mt][nt][1], c[mt][nt][2], c[mt][nt][3],
                             pa[mt].x, pb[mt].x, pa[mt].y, pb[mt].y,
                             bp[nt].x, bp[nt].y);
        }

        if (i + 2 < NT) ldgsts(i + 2, stg2); // overwrites buf(i-1): safe post-barrier
        asm volatile("cp.async.commit_group;");

        stg  = (stg  == 2) ? 0 : stg  + 1;
        stg2 = (stg2 == 2) ? 0 : stg2 + 1;
    }

    // epilogue: scale by routing weight, atomic-accumulate into out
#pragma unroll
    for (int mt = 0; mt < 4; mt++) {
#pragma unroll
        for (int half = 0; half < 2; half++) {
            const int lr  = wm * 64 + mt * 16 + g + half * 8;
            const int tok = stok[lr];
            if (tok < 0) continue;
            const float w = swt[lr];
            float* ob = out + (size_t)tok * DDIM + col0 + wn * 32 + cq * 2;
#pragma unroll
            for (int nt = 0; nt < 4; nt++) {
                atomicAdd(ob + nt * 8 + 0, w * c[mt][nt][half * 2 + 0]);
                atomicAdd(ob + nt * 8 + 1, w * c[mt][nt][half * 2 + 1]);
            }
        }
    }
}

// ---------------------------------------------------------------------------
extern "C" void kernel_launch(void* const* d_in, const int* in_sizes, int n_in,
                              void* d_out, int out_size)
{
    const float* x  = (const float*)d_in[0];   // [4,2048,1024]
    const float* gW = (const float*)d_in[1];   // [1024,8]
    const float* gb = (const float*)d_in[2];   // [8]
    const float* eW = (const float*)d_in[3];   // [8,1024,1024]
    const float* eb = (const float*)d_in[4];   // [8,1024]
    float* out = (float*)d_out;                // [4,2048,1024]

    cudaFuncSetAttribute(expert_gemm_kernel,
                         cudaFuncAttributeMaxDynamicSharedMemorySize, GEMM_SMEM);

    pair_w_kernel<<<NEXP * DDIM * DDIM / 4 / 256, 256>>>(eW);  // + zero g_cnt
    gating_kernel<<<NTOK / 8, 256>>>(x, gW, gb, eb, out);      // + write g_xr
    dim3 grid(DDIM / BN, NTOK / BM, NEXP);     // (8, 64, 8); y-tiles beyond n exit
    expert_gemm_kernel<<<grid, 256, GEMM_SMEM>>>(out);
}

// round 17
// speedup vs baseline: 2.1688x; 1.0403x over previous
#include <cuda_runtime.h>
#include <cstdint>

// Problem constants
#define NTOK 8192        // B*S
#define DDIM 1024
#define NEXP 8
#define EPSV 1e-4f
#define WTHR 0.1f

// Scratch (device globals)
__device__ int   g_cnt[NEXP];
__device__ int   g_tok[NEXP][NTOK];
__device__ float g_wt [NEXP][NTOK];
__device__ float g_xr [NTOK * DDIM];           // tf32-rounded, k-pair-permuted x
__device__ float g_wp [NEXP * DDIM * DDIM];    // tf32-rounded, k-paired W
// g_wp layout: [e][r][2n+h], r = 4*(k>>3)+(k&3), h = (k>>2)&1

// tf32 round-to-nearest-away with low 13 bits cleared (== cvt.rna.tf32 bits;
// produced rel_err 2.935178e-4 in rounds 8-14).
__device__ __forceinline__ float tf32r(float f) {
    uint32_t u = __float_as_uint(f);
    u = (u + 0x1000u) & 0xFFFFE000u;
    return __uint_as_float(u);
}

#define GATE_BLOCKS (NTOK / 8)                       // 1024
#define PAIRW_BLOCKS (NEXP * DDIM * DDIM / 4 / 256)  // 8192

// ---------------------------------------------------------------------------
// Counter zeroing MUST be a separate launch: gating blocks atomicAdd g_cnt in
// the prep launch, and blocks have no ordering within a launch (round-15 bug).
// ---------------------------------------------------------------------------
__global__ void zero_counts_kernel() {
    if (threadIdx.x < NEXP) g_cnt[threadIdx.x] = 0;
}

// ---------------------------------------------------------------------------
// Fused pre-pass: blocks [0, GATE_BLOCKS) do gating + bias + x-round;
// blocks [GATE_BLOCKS, +PAIRW_BLOCKS) do W round+pair. One launch, overlapped.
// ---------------------------------------------------------------------------
__global__ __launch_bounds__(256)
void prep_kernel(const float* __restrict__ x,
                 const float* __restrict__ gW,
                 const float* __restrict__ gb,
                 const float* __restrict__ eW,
                 const float* __restrict__ eb,
                 float* __restrict__ out)
{
    __shared__ float4 sgw[DDIM * 2];              // 32KB (gating blocks only)
    const int tid  = threadIdx.x;

    if (blockIdx.x >= GATE_BLOCKS) {
        // ---- W pair/round branch ----
        const int blk = blockIdx.x - GATE_BLOCKS;
        const int i   = blk * 256 + tid;          // float4 out index
        const int e   = i >> 18;
        const int rem = i & 262143;
        const int r   = rem >> 9;                 // row 0..511
        const int j   = rem & 511;
        const int n   = j * 2;
        const int k0  = ((r >> 2) << 3) + (r & 3);
        const float2 a = *reinterpret_cast<const float2*>(
            eW + ((size_t)e * DDIM + k0) * DDIM + n);
        const float2 b = *reinterpret_cast<const float2*>(
            eW + ((size_t)e * DDIM + k0 + 4) * DDIM + n);
        float4 o;
        o.x = tf32r(a.x); o.y = tf32r(b.x); o.z = tf32r(a.y); o.w = tf32r(b.y);
        reinterpret_cast<float4*>(g_wp)[i] = o;
        return;
    }

    // ---- gating branch (routing math byte-identical to rounds 5-14) ----
    const int lane = tid & 31;

    const float4* gW4 = reinterpret_cast<const float4*>(gW);
    for (int i = tid; i < DDIM * 2; i += 256) sgw[i] = gW4[i];
    __syncthreads();

    const int warp = blockIdx.x * 8 + (tid >> 5);
    const float* xr = x + (size_t)warp * DDIM;
    float* xw = g_xr + (size_t)warp * DDIM;

    float acc[NEXP];
#pragma unroll
    for (int e = 0; e < NEXP; e++) acc[e] = 0.0f;

#pragma unroll 4
    for (int d = lane; d < DDIM; d += 32) {
        const float xv = __ldg(xr + d);
        const int o = d & 7;
        xw[(d & ~7) + ((o & 3) << 1) + (o >> 2)] = tf32r(xv);
        const float4 ga = sgw[d * 2 + 0];
        const float4 gc = sgw[d * 2 + 1];
        acc[0] = fmaf(xv, ga.x, acc[0]);
        acc[1] = fmaf(xv, ga.y, acc[1]);
        acc[2] = fmaf(xv, ga.z, acc[2]);
        acc[3] = fmaf(xv, ga.w, acc[3]);
        acc[4] = fmaf(xv, gc.x, acc[4]);
        acc[5] = fmaf(xv, gc.y, acc[5]);
        acc[6] = fmaf(xv, gc.z, acc[6]);
        acc[7] = fmaf(xv, gc.w, acc[7]);
    }
#pragma unroll
    for (int e = 0; e < NEXP; e++) {
#pragma unroll
        for (int off = 16; off > 0; off >>= 1)
            acc[e] += __shfl_xor_sync(0xffffffffu, acc[e], off);
    }

    int   i0 = 0, i1 = 0;
    float w0 = 0.f, w1 = 0.f;
    if (lane == 0) {
        float s[NEXP], p[NEXP];
        float mx = -1e30f;
#pragma unroll
        for (int e = 0; e < NEXP; e++) {
            s[e] = fmaxf(acc[e] + gb[e], EPSV);   // TEMP = 1.0
            mx = fmaxf(mx, s[e]);
        }
        float Z = 0.0f;
#pragma unroll
        for (int e = 0; e < NEXP; e++) { p[e] = expf(s[e] - mx); Z += p[e]; }
        const float invZ = 1.0f / Z;
#pragma unroll
        for (int e = 0; e < NEXP; e++) p[e] *= invZ;

        // top-2, strict '>' => lowest index wins ties (JAX semantics)
#pragma unroll
        for (int e = 1; e < NEXP; e++) if (p[e] > p[i0]) i0 = e;
        float best = -1e30f;
#pragma unroll
        for (int e = 0; e < NEXP; e++)
            if (e != i0 && p[e] > best) { best = p[e]; i1 = e; }

        w0 = fmaxf(p[i0], WTHR);
        w1 = fmaxf(p[i1], WTHR);
        const float sc = 0.5f / (w0 + w1);        // includes /K
        w0 *= sc; w1 *= sc;

        int s0 = atomicAdd(&g_cnt[i0], 1);
        g_tok[i0][s0] = warp;  g_wt[i0][s0] = w0;
        int s1 = atomicAdd(&g_cnt[i1], 1);
        g_tok[i1][s1] = warp;  g_wt[i1][s1] = w1;
    }
    i0 = __shfl_sync(0xffffffffu, i0, 0);
    i1 = __shfl_sync(0xffffffffu, i1, 0);
    w0 = __shfl_sync(0xffffffffu, w0, 0);
    w1 = __shfl_sync(0xffffffffu, w1, 0);

    const float4* b0 = reinterpret_cast<const float4*>(eb + i0 * DDIM);
    const float4* b1 = reinterpret_cast<const float4*>(eb + i1 * DDIM);
    float4* o4 = reinterpret_cast<float4*>(out + (size_t)warp * DDIM);
#pragma unroll
    for (int j = lane; j < DDIM / 4; j += 32) {
        const float4 u = __ldg(b0 + j);
        const float4 v = __ldg(b1 + j);
        float4 r;
        r.x = w0 * u.x + w1 * v.x;
        r.y = w0 * u.y + w1 * v.y;
        r.z = w0 * u.z + w1 * v.z;
        r.w = w0 * u.w + w1 * v.w;
        o4[j] = r;
    }
}

// ---------------------------------------------------------------------------
// tf32 tensor-core grouped GEMM (round-14 mainloop, float2 vector atomics).
// CTA 128x128x32, 8 warps (2 M x 4 N), warp tile 64x32 via m16n8k8.
// cp.async 3-stage ring, ONE __syncthreads per K-tile; all frag loads LDS.64.
// ---------------------------------------------------------------------------
#define BM 128
#define BN 128
#define BK 32
#define ABYTES (BM * BK * 4)        // 16384
#define BBYTES (BN * BK * 4)        // 16384 (k-paired, unpadded)
#define STAGEB (ABYTES + BBYTES)    // 32768 bytes/stage
#define NSTAGE 3
#define GEMM_SMEM (NSTAGE * STAGEB) // 98304 B

extern __shared__ uint32_t smu[];

__device__ __forceinline__ void cp16(uint32_t dst, const float* src) {
    asm volatile("cp.async.cg.shared.global [%0], [%1], 16;" :: "r"(dst), "l"(src));
}

__device__ __forceinline__ void mma_tf32(float& d0, float& d1, float& d2, float& d3,
                                         uint32_t a0, uint32_t a1, uint32_t a2, uint32_t a3,
                                         uint32_t b0, uint32_t b1)
{
    asm volatile(
        "mma.sync.aligned.m16n8k8.row.col.f32.tf32.tf32.f32 "
        "{%0,%1,%2,%3}, {%4,%5,%6,%7}, {%8,%9}, {%0,%1,%2,%3};"
        : "+f"(d0), "+f"(d1), "+f"(d2), "+f"(d3)
        : "r"(a0), "r"(a1), "r"(a2), "r"(a3), "r"(b0), "r"(b1));
}

__global__ __launch_bounds__(256, 2)
void expert_gemm_kernel(float* __restrict__ out)
{
    const int e    = blockIdx.z;
    const int n    = g_cnt[e];
    const int row0 = blockIdx.y * BM;
    if (row0 >= n) return;
    const int col0 = blockIdx.x * BN;

    __shared__ int   stok[BM];
    __shared__ float swt[BM];

    const int tid  = threadIdx.x;
    const int lane = tid & 31;
    const int wid  = tid >> 5;
    const int wm   = wid & 1;        // 0..1 : M group (64 rows)
    const int wn   = wid >> 1;       // 0..3 : N group (32 cols)
    const int g    = lane >> 2;      // 0..7
    const int cq   = lane & 3;       // 0..3

    if (tid < BM) {
        const int r = row0 + tid;
        if (r < n) { stok[tid] = g_tok[e][r]; swt[tid] = g_wt[e][r]; }
        else       { stok[tid] = -1;          swt[tid] = 0.0f; }
    }
    __syncthreads();

    // cp.async A mapping: 128 rows x 8 16B-chunks; 2 threads/row, 4 chunks each
    const int ar = tid >> 1;                 // row 0..127
    const int ac = (tid & 1) * 4;            // first chunk (0 or 4)
    const int atok = stok[ar];
    const float* asrc = g_xr + (size_t)(atok < 0 ? 0 : atok) * DDIM + ac * 4;
    const uint32_t axm = (uint32_t)(ar & 3) << 2;   // A store-side 8B-unit swizzle

    // cp.async B mapping: 16 paired rows x 64 16B-chunks; 16 threads/row, 4 each
    const int blr = tid >> 4;                // local row 0..15
    const int bj  = tid & 15;                // chunk base
    const float* bsrc = g_wp + ((size_t)e * 512 + blr) * 2048 + col0 * 2 + bj * 4;
    const uint32_t bxm = (uint32_t)(blr & 3) << 2;  // B store-side swizzle

    const uint32_t smbase = (uint32_t)__cvta_generic_to_shared(smu);

    float c[4][4][4];                        // [mtile][ntile][frag]
#pragma unroll
    for (int mt = 0; mt < 4; mt++)
#pragma unroll
        for (int nt = 0; nt < 4; nt++)
#pragma unroll
            for (int i = 0; i < 4; i++) c[mt][nt][i] = 0.0f;

    auto ldgsts = [&](int t, int stg) {
        const uint32_t off = (uint32_t)stg * STAGEB;
        const float* as = asrc + t * BK;
#pragma unroll
        for (int j = 0; j < 4; j++) {
            const uint32_t u = ((uint32_t)(2 * (ac + j)) ^ axm) * 8;
            cp16(smbase + off + (uint32_t)ar * 128 + u, as + j * 4);
        }
        const float* bs = bsrc + (size_t)t * (16 * 2048);   // 16 rows per tile
#pragma unroll
        for (int s = 0; s < 4; s++) {
            const uint32_t u = ((uint32_t)(2 * (bj + 16 * s)) ^ bxm) * 8;
            cp16(smbase + off + ABYTES + (uint32_t)blr * 1024 + u, bs + s * 64);
        }
    };

    ldgsts(0, 0);
    asm volatile("cp.async.commit_group;");
    ldgsts(1, 1);
    asm volatile("cp.async.commit_group;");

    // fragment bases
    const char* Am0 = (const char*)smu + (wm * 64 + g) * 128;
    const char* Bm0 = (const char*)smu + ABYTES + cq * 1024 + wn * 256;
    const uint32_t fxm = (uint32_t)(g & 3) << 2;    // A load-side swizzle
    const uint32_t bfm = (uint32_t)cq << 2;         // B load-side swizzle
    uint32_t offk[4];                               // A per-kb swizzled offsets
#pragma unroll
    for (int kb = 0; kb < 4; kb++)
        offk[kb] = (((uint32_t)(kb * 4 + cq)) ^ fxm) * 8;
    uint32_t boff[4][4];                            // B per-(kb,nt) offsets
#pragma unroll
    for (int kb = 0; kb < 4; kb++)
#pragma unroll
        for (int nt = 0; nt < 4; nt++)
            boff[kb][nt] = (uint32_t)kb * 4096 +
                           (((uint32_t)(nt * 8 + g)) ^ bfm) * 8;

    const int NT = DDIM / BK;                // 32
    int stg = 0, stg2 = 2;
    for (int i = 0; i < NT; i++) {
        asm volatile("cp.async.wait_group 1;");
        __syncthreads();                     // tile i visible to all warps

        const char* As = Am0 + stg * STAGEB;
        const char* Bs = Bm0 + stg * STAGEB;

#pragma unroll
        for (int kb = 0; kb < 4; kb++) {
            uint2 pa[4], pb[4];              // [mtile] : (k,k+4) pairs, rows m / m+8
#pragma unroll
            for (int mt = 0; mt < 4; mt++) {
                const char* r0 = As + mt * (16 * 128) + offk[kb];
                pa[mt] = *reinterpret_cast<const uint2*>(r0);
                pb[mt] = *reinterpret_cast<const uint2*>(r0 + 8 * 128);
            }
            uint2 bp[4];                     // [ntile] : (k,k+4) pairs
#pragma unroll
            for (int nt = 0; nt < 4; nt++)
                bp[nt] = *reinterpret_cast<const uint2*>(Bs + boff[kb][nt]);
#pragma unroll
            for (int mt = 0; mt < 4; mt++)
#pragma unroll
                for (int nt = 0; nt < 4; nt++)
                    mma_tf32(c[mt][nt][0], c[mt][nt][1], c[mt][nt][2], c[mt][nt][3],
                             pa[mt].x, pb[mt].x, pa[mt].y, pb[mt].y,
                             bp[nt].x, bp[nt].y);
        }

        if (i + 2 < NT) ldgsts(i + 2, stg2); // overwrites buf(i-1): safe post-barrier
        asm volatile("cp.async.commit_group;");

        stg  = (stg  == 2) ? 0 : stg  + 1;
        stg2 = (stg2 == 2) ? 0 : stg2 + 1;
    }

    // epilogue: scale by routing weight, vector-atomic accumulate (float2)
#pragma unroll
    for (int mt = 0; mt < 4; mt++) {
#pragma unroll
        for (int half = 0; half < 2; half++) {
            const int lr  = wm * 64 + mt * 16 + g + half * 8;
            const int tok = stok[lr];
            if (tok < 0) continue;
            const float w = swt[lr];
            float* ob = out + (size_t)tok * DDIM + col0 + wn * 32 + cq * 2;
#pragma unroll
            for (int nt = 0; nt < 4; nt++) {
                float2 v;
                v.x = w * c[mt][nt][half * 2 + 0];
                v.y = w * c[mt][nt][half * 2 + 1];
                atomicAdd(reinterpret_cast<float2*>(ob + nt * 8), v);
            }
        }
    }
}

// ---------------------------------------------------------------------------
extern "C" void kernel_launch(void* const* d_in, const int* in_sizes, int n_in,
                              void* d_out, int out_size)
{
    const float* x  = (const float*)d_in[0];   // [4,2048,1024]
    const float* gW = (const float*)d_in[1];   // [1024,8]
    const float* gb = (const float*)d_in[2];   // [8]
    const float* eW = (const float*)d_in[3];   // [8,1024,1024]
    const float* eb = (const float*)d_in[4];   // [8,1024]
    float* out = (float*)d_out;                // [4,2048,1024]

    cudaFuncSetAttribute(expert_gemm_kernel,
                         cudaFuncAttributeMaxDynamicSharedMemorySize, GEMM_SMEM);

    zero_counts_kernel<<<1, 32>>>();           // separate launch: ordering barrier
    prep_kernel<<<GATE_BLOCKS + PAIRW_BLOCKS, 256>>>(x, gW, gb, eW, eb, out);
    dim3 grid(DDIM / BN, NTOK / BM, NEXP);     // (8, 64, 8); y-tiles beyond n exit
    expert_gemm_kernel<<<grid, 256, GEMM_SMEM>>>(out);
}